// round 4
// baseline (speedup 1.0000x reference)
#include <cuda_runtime.h>
#include <cstdint>

// Problem constants
#define BB 512
#define TT 1024
#define DD 64
#define HH 128
#define GG 384   // 3*H
#define NTHR 768

// Scratch for precomputed input gates, layout [t][b][g]
__device__ float g_xg[(size_t)TT * BB * GG];

// ---------- packed fp32x2 helpers (PTX-only; ptxas won't auto-fuse) ----------
__device__ __forceinline__ unsigned long long ffma2(unsigned long long a,
                                                    unsigned long long b,
                                                    unsigned long long c) {
    unsigned long long d;
    asm("fma.rn.f32x2 %0, %1, %2, %3;" : "=l"(d) : "l"(a), "l"(b), "l"(c));
    return d;
}
__device__ __forceinline__ float f2sum(unsigned long long v) {
    float lo, hi;
    asm("mov.b64 {%0, %1}, %2;" : "=f"(lo), "=f"(hi) : "l"(v));
    return lo + hi;
}
__device__ __forceinline__ float sigmoidf_(float x) {
    return __fdividef(1.0f, 1.0f + __expf(-x));
}

// ============================================================================
// Kernel 1: xg[t][b][g] = b_ih[g] + sum_d x[b][t][d] * w_ih[g][d]
// 384 threads: lane = 4*p + d. Thread owns 4 gate rows {4rg..4rg+3}
// (rg = 8*warp + p) x 16 k-cols [16d,16d+16). Each 16B x-load feeds 8 FFMA2.
// Lane-rotation (i+d)&3 -> conflict-free LDS; butterfly shfl over d-lanes;
// lane d stores row 4rg+d  =>  g = 32*warp + lane (coalesced STG.32).
// ============================================================================
__global__ void __launch_bounds__(384, 2)
xg_kernel(const float* __restrict__ x,
          const float* __restrict__ w_ih,
          const float* __restrict__ b_ih) {
    __shared__ __align__(16) float xs[128 * DD];  // 32 KB

    const int t    = blockIdx.x >> 2;
    const int b0   = (blockIdx.x & 3) * 128;
    const int tid  = threadIdx.x;
    const int w    = tid >> 5;
    const int lane = tid & 31;
    const int d    = lane & 3;
    const int p    = lane >> 2;
    const int rg   = w * 8 + p;          // [0,96): rows 4rg..4rg+3
    const int gcol = 32 * w + lane;      // == 4*rg + d

    // Stage 128 rows of x (64 contiguous floats each) into smem
    const float4* x4 = reinterpret_cast<const float4*>(x);
    float4* xs4 = reinterpret_cast<float4*>(xs);
    for (int i = tid; i < 128 * 16; i += 384) {
        int row = i >> 4, c4 = i & 15;
        xs4[i] = x4[((size_t)(b0 + row) * TT + t) * 16 + c4];
    }

    // Weights: 4 rows x 16 cols -> 32 ULL (64 regs). wq[r*8 + 2j {,+1}]
    unsigned long long wq[32];
#pragma unroll
    for (int r = 0; r < 4; r++) {
        const unsigned long long* wp = reinterpret_cast<const unsigned long long*>(
            w_ih + (size_t)(4 * rg + r) * DD + d * 16);
#pragma unroll
        for (int j = 0; j < 8; j++) wq[r * 8 + j] = wp[j];
    }
    const float bia = b_ih[gcol];

    __syncthreads();

    float* outp = g_xg + ((size_t)t * BB + b0) * GG + gcol;
    for (int row = 0; row < 128; row++) {
        const ulonglong2* hx =
            reinterpret_cast<const ulonglong2*>(xs + row * DD + d * 16);
        unsigned long long a0 = 0, a1 = 0, a2 = 0, a3 = 0;
#pragma unroll
        for (int i = 0; i < 4; i++) {
            int j = (i + d) & 3;              // rotation: conflict-free banks
            ulonglong2 v = hx[j];
            a0 = ffma2(wq[2 * j],      v.x, a0);
            a0 = ffma2(wq[2 * j + 1],  v.y, a0);
            a1 = ffma2(wq[8 + 2 * j],  v.x, a1);
            a1 = ffma2(wq[9 + 2 * j],  v.y, a1);
            a2 = ffma2(wq[16 + 2 * j], v.x, a2);
            a2 = ffma2(wq[17 + 2 * j], v.y, a2);
            a3 = ffma2(wq[24 + 2 * j], v.x, a3);
            a3 = ffma2(wq[25 + 2 * j], v.y, a3);
        }
        float f0 = f2sum(a0), f1 = f2sum(a1), f2 = f2sum(a2), f3 = f2sum(a3);
        // butterfly over the 4 d-lanes (lane bits 0-1)
        f0 += __shfl_xor_sync(0xffffffffu, f0, 1);
        f0 += __shfl_xor_sync(0xffffffffu, f0, 2);
        f1 += __shfl_xor_sync(0xffffffffu, f1, 1);
        f1 += __shfl_xor_sync(0xffffffffu, f1, 2);
        f2 += __shfl_xor_sync(0xffffffffu, f2, 1);
        f2 += __shfl_xor_sync(0xffffffffu, f2, 2);
        f3 += __shfl_xor_sync(0xffffffffu, f3, 1);
        f3 += __shfl_xor_sync(0xffffffffu, f3, 2);
        float vsel = (d == 0) ? f0 : (d == 1) ? f1 : (d == 2) ? f2 : f3;
        outp[(size_t)row * GG] = vsel + bia;
    }
}

// ============================================================================
// Kernel 2: persistent GRU recurrence, in-warp split-K.
// 128 CTAs x 4 batch rows, 768 threads (24 warps). lane = 4q + s.
// Thread owns gate rows {2rg, 2rg+1} (rg = 8*warp + q) x k-cols [32s,32s+32).
// Split partials reduced by shfl_xor (no smem split dim); lane s==b stores
// batch b's float2 -> P_s[4][392] (pad 8 words: conflict-free stores).
// Load rotation j=(i+2s)&7 -> 4 distinct bank-groups per LDS.128.
// ============================================================================
__global__ void __launch_bounds__(NTHR, 1)
gru_kernel(const float* __restrict__ mask,
           const float* __restrict__ w_hh,
           const float* __restrict__ b_hh,
           const float* __restrict__ Wo,
           const float* __restrict__ bo,
           float* __restrict__ out) {
    __shared__ __align__(16) float h_s[4][HH];   // 2 KB
    __shared__ __align__(16) float P_s[4][392];  // ~6.1 KB, padded stride
    __shared__ float m_s[4];
    __shared__ float wo_s[2][HH];

    const int tid  = threadIdx.x;
    const int w    = tid >> 5;
    const int lane = tid & 31;
    const int s    = lane & 3;           // k-split
    const int q    = lane >> 2;
    const int rg   = w * 8 + q;          // [0,192): rows 2rg, 2rg+1
    const int b0   = blockIdx.x * 4;

    for (int i = tid; i < 4 * HH; i += NTHR) (&h_s[0][0])[i] = 0.0f;
    for (int i = tid; i < 2 * HH; i += NTHR) (&wo_s[0][0])[i] = Wo[i];

    // weights: rows 2rg, 2rg+1, cols [32s,32s+32) -> 32 ULL (64 regs)
    unsigned long long wq[32];  // wq[r*16 + 2j {,+1}]
#pragma unroll
    for (int r = 0; r < 2; r++) {
        const unsigned long long* wp = reinterpret_cast<const unsigned long long*>(
            w_hh + (size_t)(2 * rg + r) * HH + s * 32);
#pragma unroll
        for (int j = 0; j < 16; j++) wq[r * 16 + j] = wp[j];
    }

    // gate-phase cell assignment (tid < 512): cell (cb, cj)
    const int cb = (tid >> 7) & 3;
    const int cj = tid & 127;
    const bool is_cell = tid < 512;
    // biases applied in gate phase (loaded once; frees matvec registers)
    const float bhr = is_cell ? b_hh[cj] : 0.f;
    const float bhz = is_cell ? b_hh[cj + HH] : 0.f;
    const float bhn = is_cell ? b_hh[cj + 2 * HH] : 0.f;

    const float* xg_cell = g_xg + ((size_t)(b0 + cb)) * GG + cj;
    const float* mp = mask + (size_t)(b0 + (tid & 3)) * TT;
    const float bo0 = bo[0], bo1 = bo[1];
    const int hoff = s * 32;  // float offset of this split's h window

    __syncthreads();

    for (int t = 0; t < TT; t++) {
        // ---- prefetch xg + mask; latency hidden under the matvec ----
        float xr_v = 0.f, xz_v = 0.f, xn_v = 0.f;
        if (is_cell) {
            xr_v = xg_cell[0];
            xz_v = xg_cell[HH];
            xn_v = xg_cell[2 * HH];
        }
        if (tid < 4) m_s[tid] = mp[t];

        // ---- matvec + in-warp split reduction ----
#pragma unroll
        for (int b = 0; b < 4; b++) {
            const ulonglong2* hp =
                reinterpret_cast<const ulonglong2*>(&h_s[b][0] + hoff);
            unsigned long long a0 = 0, a1 = 0;
#pragma unroll
            for (int i = 0; i < 8; i++) {
                int j = (i + 2 * s) & 7;      // rotation: conflict-free
                ulonglong2 v = hp[j];         // 8-way broadcast per address
                a0 = ffma2(wq[2 * j],      v.x, a0);
                a0 = ffma2(wq[2 * j + 1],  v.y, a0);
                a1 = ffma2(wq[16 + 2 * j], v.x, a1);
                a1 = ffma2(wq[17 + 2 * j], v.y, a1);
            }
            float v0 = f2sum(a0), v1 = f2sum(a1);
            v0 += __shfl_xor_sync(0xffffffffu, v0, 1);
            v0 += __shfl_xor_sync(0xffffffffu, v0, 2);
            v1 += __shfl_xor_sync(0xffffffffu, v1, 1);
            v1 += __shfl_xor_sync(0xffffffffu, v1, 2);
            if (s == b)  // one split-lane per batch stores the reduced pair
                *reinterpret_cast<float2*>(&P_s[b][2 * rg]) = make_float2(v0, v1);
        }
        __syncthreads();

        // ---- gate phase: 512 cells, one per thread (warps 0-15) ----
        if (is_cell) {
            float r  = sigmoidf_(xr_v + bhr + P_s[cb][cj]);
            float z  = sigmoidf_(xz_v + bhz + P_s[cb][cj + HH]);
            float n  = tanhf(fmaf(r, bhn + P_s[cb][cj + 2 * HH], xn_v));
            float ho = h_s[cb][cj];
            float hnew = fmaf(z, ho - n, n);        // (1-z)*n + z*ho
            float m  = m_s[cb];
            h_s[cb][cj] = fmaf(m, hnew - ho, ho);   // m*hnew + (1-m)*ho
        }
        __syncthreads();

        // ---- logits on warps 16-23 (overlap with next step's matvec) ----
        if (tid >= 512) {
            int wv = (tid - 512) >> 5, ln = tid & 31;
            int b = wv >> 1, o = wv & 1;
            float pv = 0.0f;
#pragma unroll
            for (int qq = 0; qq < 4; qq++)
                pv = fmaf(h_s[b][ln + 32 * qq], wo_s[o][ln + 32 * qq], pv);
#pragma unroll
            for (int off = 16; off; off >>= 1)
                pv += __shfl_down_sync(0xffffffffu, pv, off);
            if (ln == 0)
                out[(((size_t)(b0 + b)) * TT + t) * 2 + o] = pv + (o ? bo1 : bo0);
        }

        xg_cell += (size_t)BB * GG;
    }
}

// ============================================================================
extern "C" void kernel_launch(void* const* d_in, const int* in_sizes, int n_in,
                              void* d_out, int out_size) {
    const float* x    = (const float*)d_in[0];
    const float* mask = (const float*)d_in[1];
    const float* w_ih = (const float*)d_in[2];
    const float* w_hh = (const float*)d_in[3];
    const float* b_ih = (const float*)d_in[4];
    const float* b_hh = (const float*)d_in[5];
    const float* Wo   = (const float*)d_in[6];
    const float* bo   = (const float*)d_in[7];
    float* out = (float*)d_out;

    xg_kernel<<<TT * 4, 384>>>(x, w_ih, b_ih);
    gru_kernel<<<BB / 4, NTHR>>>(mask, w_hh, b_hh, Wo, bo, out);
}

// round 5
// speedup vs baseline: 1.0987x; 1.0987x over previous
#include <cuda_runtime.h>
#include <cstdint>

// Problem constants
#define BB 512
#define TT 1024
#define DD 64
#define HH 128
#define GG 384   // 3*H
#define NTHR 768

// Scratch for precomputed input gates, layout [t][b][g]
__device__ float g_xg[(size_t)TT * BB * GG];

// ---------- packed fp32x2 helpers (PTX-only; ptxas won't auto-fuse) ----------
__device__ __forceinline__ unsigned long long ffma2(unsigned long long a,
                                                    unsigned long long b,
                                                    unsigned long long c) {
    unsigned long long d;
    asm("fma.rn.f32x2 %0, %1, %2, %3;" : "=l"(d) : "l"(a), "l"(b), "l"(c));
    return d;
}
__device__ __forceinline__ float f2sum(unsigned long long v) {
    float lo, hi;
    asm("mov.b64 {%0, %1}, %2;" : "=f"(lo), "=f"(hi) : "l"(v));
    return lo + hi;
}
__device__ __forceinline__ float sigmoidf_(float x) {
    return __fdividef(1.0f, 1.0f + __expf(-x));
}
__device__ __forceinline__ float tanh_fast(float x) {
    float y;
    asm("tanh.approx.f32 %0, %1;" : "=f"(y) : "f"(x));
    return y;
}

// ============================================================================
// Kernel 1: xg[t][b][g] = b_ih[g] + sum_d x[b][t][d] * w_ih[g][d]
// Grid 8192 = (t, 8 chunks of 64 batch rows). 384 threads, 2 CTAs/SM
// (16KB smem, <=84 regs). Thread g owns gate row g (32 f32x2 weight regs);
// 2 batch rows per inner iter for ILP. All LDS are warp-broadcast.
// ============================================================================
__global__ void __launch_bounds__(384, 2)
xg_kernel(const float* __restrict__ x,
          const float* __restrict__ w_ih,
          const float* __restrict__ b_ih) {
    __shared__ __align__(16) float xs[64 * DD];  // 16 KB

    const int t  = blockIdx.x >> 3;
    const int b0 = (blockIdx.x & 7) * 64;
    const int g  = threadIdx.x;

    // Stage 64 rows of x (64 contiguous floats each) into smem
    const float4* x4 = reinterpret_cast<const float4*>(x);
    float4* xs4 = reinterpret_cast<float4*>(xs);
    for (int i = threadIdx.x; i < 64 * 16; i += 384) {
        int row = i >> 4, c4 = i & 15;
        xs4[i] = x4[((size_t)(b0 + row) * TT + t) * 16 + c4];
    }

    // This thread's w_ih row -> 32 packed pairs (64 regs)
    unsigned long long wq[32];
    const unsigned long long* wp =
        reinterpret_cast<const unsigned long long*>(w_ih + (size_t)g * DD);
#pragma unroll
    for (int i = 0; i < 32; i++) wq[i] = wp[i];
    const unsigned long long accInit =
        (unsigned long long)__float_as_uint(b_ih[g]);  // (bias, 0)

    __syncthreads();

    float* outp = g_xg + ((size_t)t * BB + b0) * GG + g;
#pragma unroll 1
    for (int row = 0; row < 64; row += 2) {
        const ulonglong2* hx0 =
            reinterpret_cast<const ulonglong2*>(xs + row * DD);
        const ulonglong2* hx1 =
            reinterpret_cast<const ulonglong2*>(xs + (row + 1) * DD);
        unsigned long long acc0 = accInit, acc1 = accInit;
#pragma unroll
        for (int i = 0; i < 16; i++) {
            ulonglong2 v0 = hx0[i];  // broadcast LDS.128
            acc0 = ffma2(wq[2 * i], v0.x, acc0);
            acc0 = ffma2(wq[2 * i + 1], v0.y, acc0);
            ulonglong2 v1 = hx1[i];
            acc1 = ffma2(wq[2 * i], v1.x, acc1);
            acc1 = ffma2(wq[2 * i + 1], v1.y, acc1);
        }
        outp[(size_t)row * GG]       = f2sum(acc0);
        outp[(size_t)(row + 1) * GG] = f2sum(acc1);
    }
}

// ============================================================================
// Kernel 2: persistent GRU recurrence (R3 matvec structure — best measured).
// 128 CTAs x 4 batch rows, 768 threads. Thread (s, grp) owns gate rows
// {2grp, 2grp+1} x k-cols [32s, 32s+32): 32 f32x2 weight regs, ratio-4.
// NEW vs R3: h double-buffered; logits for step t-1 run on warps 16-23
// DURING the gate phase of step t (no post-barrier tail); tanh.approx.
// ============================================================================
__global__ void __launch_bounds__(NTHR, 1)
gru_kernel(const float* __restrict__ mask,
           const float* __restrict__ w_hh,
           const float* __restrict__ b_hh,
           const float* __restrict__ Wo,
           const float* __restrict__ bo,
           float* __restrict__ out) {
    __shared__ __align__(16) float h_s[2][4][HH];   // 4 KB double-buffered
    __shared__ __align__(16) float P_s[4][4][GG];   // 24 KB: [split][batch][g]
    __shared__ float m_s[4];
    __shared__ float wo_s[2][HH];

    const int tid = threadIdx.x;
    const int s   = tid / 192;          // k-split, warp-uniform (192 = 6 warps)
    const int grp = tid - s * 192;      // row group: rows 2grp, 2grp+1
    const int b0  = blockIdx.x * 4;

    for (int i = tid; i < 4 * HH; i += NTHR) (&h_s[0][0][0])[i] = 0.0f;
    for (int i = tid; i < 2 * HH; i += NTHR) (&wo_s[0][0])[i] = Wo[i];

    // weights: rows 2grp..2grp+1, cols [32s, 32s+32) -> 32 packed pairs
    unsigned long long wq[32];  // wq[r*16 + j]
#pragma unroll
    for (int r = 0; r < 2; r++) {
        const unsigned long long* wp = reinterpret_cast<const unsigned long long*>(
            w_hh + (size_t)(2 * grp + r) * HH + s * 32);
#pragma unroll
        for (int j = 0; j < 16; j++) wq[r * 16 + j] = wp[j];
    }
    // bias contributed once, by split 0 only
    const unsigned long long bias0 =
        (s == 0) ? (unsigned long long)__float_as_uint(b_hh[2 * grp]) : 0ull;
    const unsigned long long bias1 =
        (s == 0) ? (unsigned long long)__float_as_uint(b_hh[2 * grp + 1]) : 0ull;

    // gate-phase cell assignment (tid < 512): cell (cb, cj)
    const int cb = (tid >> 7) & 3;
    const int cj = tid & 127;
    const bool is_cell = tid < 512;

    // logits assignment (warps 16-23)
    const int lw   = (tid - 512) >> 5;   // 0..7 for tid>=512
    const int lb   = lw >> 1, lo_ = lw & 1;
    const int lln  = tid & 31;

    const float* xg_cell = g_xg + ((size_t)(b0 + cb)) * GG + cj; // step 0
    const float* mp = mask + (size_t)(b0 + (tid & 3)) * TT;
    const float bo0 = bo[0], bo1 = bo[1];

    // partial store slot: P_s[s][b][2grp..2grp+1] as float2
    float2* Pst = reinterpret_cast<float2*>(&P_s[s][0][0]) + grp;

    __syncthreads();

    int p = 0;  // h parity: matvec reads h_s[p], gate writes h_s[p^1]
    for (int t = 0; t < TT; t++) {
        // ---- prefetch xg (gate-phase regs) + mask; hidden under matvec ----
        float xr_v = 0.f, xz_v = 0.f, xn_v = 0.f;
        if (is_cell) {
            xr_v = xg_cell[0];
            xz_v = xg_cell[HH];
            xn_v = xg_cell[2 * HH];
        }
        if (tid < 4) m_s[tid] = mp[t];

        // ---- matvec: P[s][b][2grp+r] = bias? + h[p][b][32s..+32) . w[r] ----
        const float* hbase = &h_s[p][0][0] + s * 32;
#pragma unroll
        for (int bp = 0; bp < 2; bp++) {  // batch pairs (0,1), (2,3)
            const ulonglong2* hA =
                reinterpret_cast<const ulonglong2*>(hbase + (2 * bp) * HH);
            const ulonglong2* hB =
                reinterpret_cast<const ulonglong2*>(hbase + (2 * bp + 1) * HH);
            unsigned long long a0 = bias0, a1 = bias1;
            unsigned long long c0 = bias0, c1 = bias1;
#pragma unroll
            for (int i = 0; i < 8; i++) {
                ulonglong2 vA = hA[i];  // broadcast LDS.128
                a0 = ffma2(wq[2 * i],      vA.x, a0);
                a0 = ffma2(wq[2 * i + 1],  vA.y, a0);
                a1 = ffma2(wq[16 + 2 * i], vA.x, a1);
                a1 = ffma2(wq[17 + 2 * i], vA.y, a1);
                ulonglong2 vB = hB[i];
                c0 = ffma2(wq[2 * i],      vB.x, c0);
                c0 = ffma2(wq[2 * i + 1],  vB.y, c0);
                c1 = ffma2(wq[16 + 2 * i], vB.x, c1);
                c1 = ffma2(wq[17 + 2 * i], vB.y, c1);
            }
            Pst[(2 * bp) * 192]     = make_float2(f2sum(a0), f2sum(a1));
            Pst[(2 * bp + 1) * 192] = make_float2(f2sum(c0), f2sum(c1));
        }
        __syncthreads();

        // ---- gate phase (warps 0-15) + logits for step t-1 (warps 16-23) ----
        if (is_cell) {
            float sr = xr_v, sz = xz_v, sn = 0.0f;
#pragma unroll
            for (int k = 0; k < 4; k++) {
                sr += P_s[k][cb][cj];
                sz += P_s[k][cb][cj + HH];
                sn += P_s[k][cb][cj + 2 * HH];
            }
            float r  = sigmoidf_(sr);
            float z  = sigmoidf_(sz);
            float n  = tanh_fast(fmaf(r, sn, xn_v));
            float ho = h_s[p][cb][cj];
            float hnew = fmaf(z, ho - n, n);          // (1-z)*n + z*ho
            float m  = m_s[cb];
            h_s[p ^ 1][cb][cj] = fmaf(m, hnew - ho, ho);
        } else if (t > 0) {
            // logits for step t-1: h after step t-1 lives in h_s[p]
            float pv = 0.0f;
#pragma unroll
            for (int qq = 0; qq < 4; qq++)
                pv = fmaf(h_s[p][lb][lln + 32 * qq], wo_s[lo_][lln + 32 * qq], pv);
#pragma unroll
            for (int off = 16; off; off >>= 1)
                pv += __shfl_down_sync(0xffffffffu, pv, off);
            if (lln == 0)
                out[(((size_t)(b0 + lb)) * TT + (t - 1)) * 2 + lo_] =
                    pv + (lo_ ? bo1 : bo0);
        }
        __syncthreads();

        p ^= 1;
        xg_cell += (size_t)BB * GG;
    }

    // final logits for t = TT-1 (h lives in h_s[p])
    if (tid >= 512) {
        float pv = 0.0f;
#pragma unroll
        for (int qq = 0; qq < 4; qq++)
            pv = fmaf(h_s[p][lb][lln + 32 * qq], wo_s[lo_][lln + 32 * qq], pv);
#pragma unroll
        for (int off = 16; off; off >>= 1)
            pv += __shfl_down_sync(0xffffffffu, pv, off);
        if (lln == 0)
            out[(((size_t)(b0 + lb)) * TT + (TT - 1)) * 2 + lo_] =
                pv + (lo_ ? bo1 : bo0);
    }
}

// ============================================================================
extern "C" void kernel_launch(void* const* d_in, const int* in_sizes, int n_in,
                              void* d_out, int out_size) {
    const float* x    = (const float*)d_in[0];
    const float* mask = (const float*)d_in[1];
    const float* w_ih = (const float*)d_in[2];
    const float* w_hh = (const float*)d_in[3];
    const float* b_ih = (const float*)d_in[4];
    const float* b_hh = (const float*)d_in[5];
    const float* Wo   = (const float*)d_in[6];
    const float* bo   = (const float*)d_in[7];
    float* out = (float*)d_out;

    xg_kernel<<<TT * 8, 384>>>(x, w_ih, b_ih);
    gru_kernel<<<BB / 4, NTHR>>>(mask, w_hh, b_hh, Wo, bo, out);
}

// round 6
// speedup vs baseline: 1.1922x; 1.0851x over previous
#include <cuda_runtime.h>
#include <cstdint>

// Problem constants
#define BB 512
#define TT 1024
#define DD 64
#define HH 128
#define GG 384   // 3*H
#define NTHR 768

// Scratch for precomputed input gates, layout [t][b][g]
__device__ float g_xg[(size_t)TT * BB * GG];

// ---------- packed fp32x2 helpers (PTX-only; ptxas won't auto-fuse) ----------
__device__ __forceinline__ unsigned long long ffma2(unsigned long long a,
                                                    unsigned long long b,
                                                    unsigned long long c) {
    unsigned long long d;
    asm("fma.rn.f32x2 %0, %1, %2, %3;" : "=l"(d) : "l"(a), "l"(b), "l"(c));
    return d;
}
__device__ __forceinline__ float f2sum(unsigned long long v) {
    float lo, hi;
    asm("mov.b64 {%0, %1}, %2;" : "=f"(lo), "=f"(hi) : "l"(v));
    return lo + hi;
}
__device__ __forceinline__ float tanh_fast(float x) {
    float y;
    asm("tanh.approx.f32 %0, %1;" : "=f"(y) : "f"(x));
    return y;
}
// sigmoid(x) = 0.5 + 0.5*tanh(x/2): one MUFU.TANH + 2 FMA
__device__ __forceinline__ float sigmoid_fast(float x) {
    return fmaf(tanh_fast(0.5f * x), 0.5f, 0.5f);
}

// ============================================================================
// Kernel 1: xg[t][b][g] = b_ih[g] + sum_d x[b][t][d] * w_ih[g][d]
// 384 threads, 2 CTAs/SM. Thread (s = tid/192, grp = tid%192) owns w_ih rows
// {2grp, 2grp+1} x cols [32s, 32s+32): 64 weight floats, ratio 4
// (each broadcast LDS.128 feeds 4 FFMA2 — the trick that worked in gru-R3).
// 64 batch rows per CTA, processed in 8 phases of 8 rows; 2-split partials
// reduced through a 24 KB smem P array; output STG fully coalesced over g.
// ============================================================================
__global__ void __launch_bounds__(384, 2)
xg_kernel(const float* __restrict__ x,
          const float* __restrict__ w_ih,
          const float* __restrict__ b_ih) {
    __shared__ __align__(16) float xs[64 * DD];     // 16 KB
    __shared__ __align__(16) float P[2][8][GG];     // 24 KB

    const int t   = blockIdx.x >> 3;
    const int b0  = (blockIdx.x & 7) * 64;
    const int tid = threadIdx.x;
    const int s   = tid / 192;      // k-split (warps 0-5: s=0, 6-11: s=1)
    const int grp = tid - s * 192;  // rows 2grp, 2grp+1

    // Stage 64 rows of x (64 contiguous floats each) into smem
    const float4* x4 = reinterpret_cast<const float4*>(x);
    float4* xs4 = reinterpret_cast<float4*>(xs);
    for (int i = tid; i < 64 * 16; i += 384) {
        int row = i >> 4, c4 = i & 15;
        xs4[i] = x4[((size_t)(b0 + row) * TT + t) * 16 + c4];
    }

    // Weights: rows 2grp..2grp+1, cols [32s, 32s+32) -> 32 ULL (64 regs)
    unsigned long long wq[32];  // wq[r*16 + j]
#pragma unroll
    for (int r = 0; r < 2; r++) {
        const unsigned long long* wp = reinterpret_cast<const unsigned long long*>(
            w_ih + (size_t)(2 * grp + r) * DD + s * 32);
#pragma unroll
        for (int j = 0; j < 16; j++) wq[r * 16 + j] = wp[j];
    }
    const float bia = b_ih[tid];  // for the output phase (g = tid)

    __syncthreads();

#pragma unroll 1
    for (int ph = 0; ph < 8; ph++) {
        const float* xbase = xs + (ph * 8) * DD + s * 32;
        // 8 rows, one at a time (2 accumulator chains/thread: enough ILP
        // to saturate the rt-2 fma pipe at 6 warps/SMSP)
#pragma unroll
        for (int r = 0; r < 8; r++) {
            const ulonglong2* hx =
                reinterpret_cast<const ulonglong2*>(xbase + r * DD);
            unsigned long long a0 = 0, a1 = 0;
#pragma unroll
            for (int i = 0; i < 8; i++) {
                ulonglong2 v = hx[i];  // broadcast LDS.128
                a0 = ffma2(wq[2 * i],      v.x, a0);
                a0 = ffma2(wq[2 * i + 1],  v.y, a0);
                a1 = ffma2(wq[16 + 2 * i], v.x, a1);
                a1 = ffma2(wq[17 + 2 * i], v.y, a1);
            }
            *reinterpret_cast<float2*>(&P[s][r][2 * grp]) =
                make_float2(f2sum(a0), f2sum(a1));
        }
        __syncthreads();

        // output: thread owns g = tid for all 8 rows (coalesced STG.32)
        float* op = g_xg + ((size_t)t * BB + b0 + ph * 8) * GG + tid;
#pragma unroll
        for (int r = 0; r < 8; r++)
            op[(size_t)r * GG] = P[0][r][tid] + P[1][r][tid] + bia;
        __syncthreads();
    }
}

// ============================================================================
// Kernel 2: persistent GRU recurrence — exact R3 structure (best measured),
// only the gate activations swapped to MUFU.TANH-based fast forms.
// 128 CTAs x 4 batch rows, 768 threads. Thread (s, grp) owns gate rows
// {2grp, 2grp+1} x k-cols [32s, 32s+32): ratio 4. Logits on warps 16-23
// after the 2nd barrier, overlapping the next step's matvec.
// ============================================================================
__global__ void __launch_bounds__(NTHR, 1)
gru_kernel(const float* __restrict__ mask,
           const float* __restrict__ w_hh,
           const float* __restrict__ b_hh,
           const float* __restrict__ Wo,
           const float* __restrict__ bo,
           float* __restrict__ out) {
    __shared__ __align__(16) float h_s[4][HH];      // 2 KB
    __shared__ __align__(16) float P_s[4][4][GG];   // 24 KB: [split][batch][g]
    __shared__ float m_s[4];
    __shared__ float wo_s[2][HH];

    const int tid = threadIdx.x;
    const int s   = tid / 192;          // k-split, warp-uniform
    const int grp = tid - s * 192;      // rows 2grp, 2grp+1
    const int b0  = blockIdx.x * 4;

    for (int i = tid; i < 4 * HH; i += NTHR) (&h_s[0][0])[i] = 0.0f;
    for (int i = tid; i < 2 * HH; i += NTHR) (&wo_s[0][0])[i] = Wo[i];

    unsigned long long wq[32];  // wq[r*16 + j]
#pragma unroll
    for (int r = 0; r < 2; r++) {
        const unsigned long long* wp = reinterpret_cast<const unsigned long long*>(
            w_hh + (size_t)(2 * grp + r) * HH + s * 32);
#pragma unroll
        for (int j = 0; j < 16; j++) wq[r * 16 + j] = wp[j];
    }
    const unsigned long long bias0 =
        (s == 0) ? (unsigned long long)__float_as_uint(b_hh[2 * grp]) : 0ull;
    const unsigned long long bias1 =
        (s == 0) ? (unsigned long long)__float_as_uint(b_hh[2 * grp + 1]) : 0ull;

    const int cb = (tid >> 7) & 3;
    const int cj = tid & 127;
    const bool is_cell = tid < 512;

    const float* xg_cell = g_xg + ((size_t)(b0 + cb)) * GG + cj;
    const float* mp = mask + (size_t)(b0 + (tid & 3)) * TT;
    const float bo0 = bo[0], bo1 = bo[1];

    float2* Pst = reinterpret_cast<float2*>(&P_s[s][0][0]) + grp;

    __syncthreads();

    for (int t = 0; t < TT; t++) {
        // ---- prefetch xg + mask; hidden under matvec ----
        float xr_v = 0.f, xz_v = 0.f, xn_v = 0.f;
        if (is_cell) {
            xr_v = xg_cell[0];
            xz_v = xg_cell[HH];
            xn_v = xg_cell[2 * HH];
        }
        if (tid < 4) m_s[tid] = mp[t];

        // ---- matvec: P[s][b][2grp+r] = bias? + h[b][32s..+32) . w[r] ----
        const float* hbase = &h_s[0][0] + s * 32;
#pragma unroll
        for (int bp = 0; bp < 2; bp++) {
            const ulonglong2* hA =
                reinterpret_cast<const ulonglong2*>(hbase + (2 * bp) * HH);
            const ulonglong2* hB =
                reinterpret_cast<const ulonglong2*>(hbase + (2 * bp + 1) * HH);
            unsigned long long a0 = bias0, a1 = bias1;
            unsigned long long c0 = bias0, c1 = bias1;
#pragma unroll
            for (int i = 0; i < 8; i++) {
                ulonglong2 vA = hA[i];  // broadcast LDS.128
                a0 = ffma2(wq[2 * i],      vA.x, a0);
                a0 = ffma2(wq[2 * i + 1],  vA.y, a0);
                a1 = ffma2(wq[16 + 2 * i], vA.x, a1);
                a1 = ffma2(wq[17 + 2 * i], vA.y, a1);
                ulonglong2 vB = hB[i];
                c0 = ffma2(wq[2 * i],      vB.x, c0);
                c0 = ffma2(wq[2 * i + 1],  vB.y, c0);
                c1 = ffma2(wq[16 + 2 * i], vB.x, c1);
                c1 = ffma2(wq[17 + 2 * i], vB.y, c1);
            }
            Pst[(2 * bp) * 192]     = make_float2(f2sum(a0), f2sum(a1));
            Pst[(2 * bp + 1) * 192] = make_float2(f2sum(c0), f2sum(c1));
        }
        __syncthreads();

        // ---- gate phase: 512 cells, one per thread (warps 0-15) ----
        if (is_cell) {
            float sr = xr_v, sz = xz_v, sn = 0.0f;
#pragma unroll
            for (int k = 0; k < 4; k++) {
                sr += P_s[k][cb][cj];
                sz += P_s[k][cb][cj + HH];
                sn += P_s[k][cb][cj + 2 * HH];
            }
            float r  = sigmoid_fast(sr);
            float z  = sigmoid_fast(sz);
            float n  = tanh_fast(fmaf(r, sn, xn_v));
            float ho = h_s[cb][cj];
            float hnew = fmaf(z, ho - n, n);        // (1-z)*n + z*ho
            float m  = m_s[cb];
            h_s[cb][cj] = fmaf(m, hnew - ho, ho);   // m*hnew + (1-m)*ho
        }
        __syncthreads();

        // ---- logits on warps 16-23: overlaps next step's matvec (R3) ----
        if (tid >= 512) {
            int w = (tid - 512) >> 5, lane = tid & 31;
            int b = w >> 1, o = w & 1;
            float pv = 0.0f;
#pragma unroll
            for (int q = 0; q < 4; q++)
                pv = fmaf(h_s[b][lane + 32 * q], wo_s[o][lane + 32 * q], pv);
#pragma unroll
            for (int off = 16; off; off >>= 1)
                pv += __shfl_down_sync(0xffffffffu, pv, off);
            if (lane == 0)
                out[(((size_t)(b0 + b)) * TT + t) * 2 + o] = pv + (o ? bo1 : bo0);
        }

        xg_cell += (size_t)BB * GG;
    }
}

// ============================================================================
extern "C" void kernel_launch(void* const* d_in, const int* in_sizes, int n_in,
                              void* d_out, int out_size) {
    const float* x    = (const float*)d_in[0];
    const float* mask = (const float*)d_in[1];
    const float* w_ih = (const float*)d_in[2];
    const float* w_hh = (const float*)d_in[3];
    const float* b_ih = (const float*)d_in[4];
    const float* b_hh = (const float*)d_in[5];
    const float* Wo   = (const float*)d_in[6];
    const float* bo   = (const float*)d_in[7];
    float* out = (float*)d_out;

    xg_kernel<<<TT * 8, 384>>>(x, w_ih, b_ih);
    gru_kernel<<<BB / 4, NTHR>>>(mask, w_hh, b_hh, Wo, bo, out);
}

// round 7
// speedup vs baseline: 1.2769x; 1.0711x over previous
#include <cuda_runtime.h>
#include <cstdint>

// Problem constants
#define BB 512
#define TT 1024
#define DD 64
#define HH 128
#define GG 384   // 3*H
#define NTHR 768

// Scratch for precomputed input gates, layout [t][b][g]
__device__ float g_xg[(size_t)TT * BB * GG];

// ---------- packed fp32x2 helpers (PTX-only; ptxas won't auto-fuse) ----------
__device__ __forceinline__ unsigned long long ffma2(unsigned long long a,
                                                    unsigned long long b,
                                                    unsigned long long c) {
    unsigned long long d;
    asm("fma.rn.f32x2 %0, %1, %2, %3;" : "=l"(d) : "l"(a), "l"(b), "l"(c));
    return d;
}
__device__ __forceinline__ float f2sum(unsigned long long v) {
    float lo, hi;
    asm("mov.b64 {%0, %1}, %2;" : "=f"(lo), "=f"(hi) : "l"(v));
    return lo + hi;
}
__device__ __forceinline__ float tanh_fast(float x) {
    float y;
    asm("tanh.approx.f32 %0, %1;" : "=f"(y) : "f"(x));
    return y;
}
// sigmoid(x) = 0.5 + 0.5*tanh(x/2): one MUFU.TANH + 2 FMA
__device__ __forceinline__ float sigmoid_fast(float x) {
    return fmaf(tanh_fast(0.5f * x), 0.5f, 0.5f);
}

// ============================================================================
// Kernel 1: xg[t][b][g] = b_ih[g] + sum_d x[b][t][d] * w_ih[g][d]
// R1 skeleton (no split, no reduction, no phase barriers) + ratio-4:
// 192 threads, 2 CTAs/SM. Thread owns gate rows g=tid and g=tid+192, FULL
// 64 k-cols each -> 64 ULL weight regs (128 floats). Each broadcast LDS.128
// feeds 4 FFMA2. Per x-row: 16 LDS + 64 FFMA2 + 2 coalesced STG.32.
// 4096 CTAs = (t, 4 chunks of 128 batch rows).
// ============================================================================
__global__ void __launch_bounds__(192, 2)
xg_kernel(const float* __restrict__ x,
          const float* __restrict__ w_ih,
          const float* __restrict__ b_ih) {
    __shared__ __align__(16) float xs[128 * DD];  // 32 KB (x2 CTAs = 64 KB/SM)

    const int t   = blockIdx.x >> 2;
    const int b0  = (blockIdx.x & 3) * 128;
    const int tid = threadIdx.x;  // gate rows tid, tid+192

    // Stage 128 rows of x (64 contiguous floats each) into smem
    const float4* x4 = reinterpret_cast<const float4*>(x);
    float4* xs4 = reinterpret_cast<float4*>(xs);
    for (int i = tid; i < 128 * 16; i += 192) {
        int row = i >> 4, c4 = i & 15;
        xs4[i] = x4[((size_t)(b0 + row) * TT + t) * 16 + c4];
    }

    // Weights: rows tid (wq[0..31]) and tid+192 (wq[32..63]) -> 128 regs
    unsigned long long wq[64];
    {
        const unsigned long long* wp0 =
            reinterpret_cast<const unsigned long long*>(w_ih + (size_t)tid * DD);
        const unsigned long long* wp1 = reinterpret_cast<const unsigned long long*>(
            w_ih + (size_t)(tid + 192) * DD);
#pragma unroll
        for (int i = 0; i < 32; i++) wq[i] = wp0[i];
#pragma unroll
        for (int i = 0; i < 32; i++) wq[32 + i] = wp1[i];
    }
    const float bia0 = b_ih[tid];
    const float bia1 = b_ih[tid + 192];

    __syncthreads();

    float* outp = g_xg + ((size_t)t * BB + b0) * GG + tid;
#pragma unroll 1
    for (int row = 0; row < 128; row++) {
        const ulonglong2* hx =
            reinterpret_cast<const ulonglong2*>(xs + row * DD);
        unsigned long long a0 = 0ull, a1 = 0ull;  // two independent chains
#pragma unroll
        for (int i = 0; i < 16; i++) {
            ulonglong2 v = hx[i];  // broadcast LDS.128 (warp-uniform addr)
            a0 = ffma2(wq[2 * i],      v.x, a0);
            a0 = ffma2(wq[2 * i + 1],  v.y, a0);
            a1 = ffma2(wq[32 + 2 * i], v.x, a1);
            a1 = ffma2(wq[33 + 2 * i], v.y, a1);
        }
        outp[0]   = f2sum(a0) + bia0;   // g = tid       (coalesced STG.32)
        outp[192] = f2sum(a1) + bia1;   // g = tid + 192 (coalesced STG.32)
        outp += GG;
    }
}

// ============================================================================
// Kernel 2: persistent GRU recurrence — UNCHANGED from R6 (best measured:
// 2357us). R3 structure, ratio-4 matvec, MUFU.TANH activations, logits on
// warps 16-23 overlapping the next step's matvec.
// ============================================================================
__global__ void __launch_bounds__(NTHR, 1)
gru_kernel(const float* __restrict__ mask,
           const float* __restrict__ w_hh,
           const float* __restrict__ b_hh,
           const float* __restrict__ Wo,
           const float* __restrict__ bo,
           float* __restrict__ out) {
    __shared__ __align__(16) float h_s[4][HH];      // 2 KB
    __shared__ __align__(16) float P_s[4][4][GG];   // 24 KB: [split][batch][g]
    __shared__ float m_s[4];
    __shared__ float wo_s[2][HH];

    const int tid = threadIdx.x;
    const int s   = tid / 192;          // k-split, warp-uniform
    const int grp = tid - s * 192;      // rows 2grp, 2grp+1
    const int b0  = blockIdx.x * 4;

    for (int i = tid; i < 4 * HH; i += NTHR) (&h_s[0][0])[i] = 0.0f;
    for (int i = tid; i < 2 * HH; i += NTHR) (&wo_s[0][0])[i] = Wo[i];

    unsigned long long wq[32];  // wq[r*16 + j]
#pragma unroll
    for (int r = 0; r < 2; r++) {
        const unsigned long long* wp = reinterpret_cast<const unsigned long long*>(
            w_hh + (size_t)(2 * grp + r) * HH + s * 32);
#pragma unroll
        for (int j = 0; j < 16; j++) wq[r * 16 + j] = wp[j];
    }
    const unsigned long long bias0 =
        (s == 0) ? (unsigned long long)__float_as_uint(b_hh[2 * grp]) : 0ull;
    const unsigned long long bias1 =
        (s == 0) ? (unsigned long long)__float_as_uint(b_hh[2 * grp + 1]) : 0ull;

    const int cb = (tid >> 7) & 3;
    const int cj = tid & 127;
    const bool is_cell = tid < 512;

    const float* xg_cell = g_xg + ((size_t)(b0 + cb)) * GG + cj;
    const float* mp = mask + (size_t)(b0 + (tid & 3)) * TT;
    const float bo0 = bo[0], bo1 = bo[1];

    float2* Pst = reinterpret_cast<float2*>(&P_s[s][0][0]) + grp;

    __syncthreads();

    for (int t = 0; t < TT; t++) {
        // ---- prefetch xg + mask; hidden under matvec ----
        float xr_v = 0.f, xz_v = 0.f, xn_v = 0.f;
        if (is_cell) {
            xr_v = xg_cell[0];
            xz_v = xg_cell[HH];
            xn_v = xg_cell[2 * HH];
        }
        if (tid < 4) m_s[tid] = mp[t];

        // ---- matvec: P[s][b][2grp+r] = bias? + h[b][32s..+32) . w[r] ----
        const float* hbase = &h_s[0][0] + s * 32;
#pragma unroll
        for (int bp = 0; bp < 2; bp++) {
            const ulonglong2* hA =
                reinterpret_cast<const ulonglong2*>(hbase + (2 * bp) * HH);
            const ulonglong2* hB =
                reinterpret_cast<const ulonglong2*>(hbase + (2 * bp + 1) * HH);
            unsigned long long a0 = bias0, a1 = bias1;
            unsigned long long c0 = bias0, c1 = bias1;
#pragma unroll
            for (int i = 0; i < 8; i++) {
                ulonglong2 vA = hA[i];  // broadcast LDS.128
                a0 = ffma2(wq[2 * i],      vA.x, a0);
                a0 = ffma2(wq[2 * i + 1],  vA.y, a0);
                a1 = ffma2(wq[16 + 2 * i], vA.x, a1);
                a1 = ffma2(wq[17 + 2 * i], vA.y, a1);
                ulonglong2 vB = hB[i];
                c0 = ffma2(wq[2 * i],      vB.x, c0);
                c0 = ffma2(wq[2 * i + 1],  vB.y, c0);
                c1 = ffma2(wq[16 + 2 * i], vB.x, c1);
                c1 = ffma2(wq[17 + 2 * i], vB.y, c1);
            }
            Pst[(2 * bp) * 192]     = make_float2(f2sum(a0), f2sum(a1));
            Pst[(2 * bp + 1) * 192] = make_float2(f2sum(c0), f2sum(c1));
        }
        __syncthreads();

        // ---- gate phase: 512 cells, one per thread (warps 0-15) ----
        if (is_cell) {
            float sr = xr_v, sz = xz_v, sn = 0.0f;
#pragma unroll
            for (int k = 0; k < 4; k++) {
                sr += P_s[k][cb][cj];
                sz += P_s[k][cb][cj + HH];
                sn += P_s[k][cb][cj + 2 * HH];
            }
            float r  = sigmoid_fast(sr);
            float z  = sigmoid_fast(sz);
            float n  = tanh_fast(fmaf(r, sn, xn_v));
            float ho = h_s[cb][cj];
            float hnew = fmaf(z, ho - n, n);        // (1-z)*n + z*ho
            float m  = m_s[cb];
            h_s[cb][cj] = fmaf(m, hnew - ho, ho);   // m*hnew + (1-m)*ho
        }
        __syncthreads();

        // ---- logits on warps 16-23: overlaps next step's matvec ----
        if (tid >= 512) {
            int w = (tid - 512) >> 5, lane = tid & 31;
            int b = w >> 1, o = w & 1;
            float pv = 0.0f;
#pragma unroll
            for (int q = 0; q < 4; q++)
                pv = fmaf(h_s[b][lane + 32 * q], wo_s[o][lane + 32 * q], pv);
#pragma unroll
            for (int off = 16; off; off >>= 1)
                pv += __shfl_down_sync(0xffffffffu, pv, off);
            if (lane == 0)
                out[(((size_t)(b0 + b)) * TT + t) * 2 + o] = pv + (o ? bo1 : bo0);
        }

        xg_cell += (size_t)BB * GG;
    }
}

// ============================================================================
extern "C" void kernel_launch(void* const* d_in, const int* in_sizes, int n_in,
                              void* d_out, int out_size) {
    const float* x    = (const float*)d_in[0];
    const float* mask = (const float*)d_in[1];
    const float* w_ih = (const float*)d_in[2];
    const float* w_hh = (const float*)d_in[3];
    const float* b_ih = (const float*)d_in[4];
    const float* b_hh = (const float*)d_in[5];
    const float* Wo   = (const float*)d_in[6];
    const float* bo   = (const float*)d_in[7];
    float* out = (float*)d_out;

    xg_kernel<<<TT * 4, 192>>>(x, w_ih, b_ih);
    gru_kernel<<<BB / 4, NTHR>>>(mask, w_hh, b_hh, Wo, bo, out);
}

// round 8
// speedup vs baseline: 1.3391x; 1.0487x over previous
#include <cuda_runtime.h>
#include <cstdint>

// Problem constants
#define BB 512
#define TT 1024
#define DD 64
#define HH 128
#define GG 384   // 3*H
#define NTHR 768

// Scratch for precomputed input gates, layout [t][b][g]
__device__ float g_xg[(size_t)TT * BB * GG];

// ---------- packed fp32x2 helpers (PTX-only; ptxas won't auto-fuse) ----------
__device__ __forceinline__ unsigned long long ffma2(unsigned long long a,
                                                    unsigned long long b,
                                                    unsigned long long c) {
    unsigned long long d;
    asm("fma.rn.f32x2 %0, %1, %2, %3;" : "=l"(d) : "l"(a), "l"(b), "l"(c));
    return d;
}
__device__ __forceinline__ float f2sum(unsigned long long v) {
    float lo, hi;
    asm("mov.b64 {%0, %1}, %2;" : "=f"(lo), "=f"(hi) : "l"(v));
    return lo + hi;
}
__device__ __forceinline__ float tanh_fast(float x) {
    float y;
    asm("tanh.approx.f32 %0, %1;" : "=f"(y) : "f"(x));
    return y;
}
__device__ __forceinline__ float sigmoid_fast(float x) {
    return fmaf(tanh_fast(0.5f * x), 0.5f, 0.5f);
}

// ============================================================================
// Kernel 1: xg[t][b][g] = b_ih[g] + sum_d x[b][t][d] * w_ih[g][d]
// 192 threads, 2 CTAs/SM. Thread (q = tid>>1, s = tid&1) owns gate rows
// 4q..4q+3 x k-cols [32s, 32s+32): ratio 8 FFMA2 per LDS.128 -> smem data
// return (128B/thread/row) balanced with the FMA pipe. Lane-pair k-split
// combined by one shfl_xor(1) per row; coalesced float2 STG.
// ============================================================================
__global__ void __launch_bounds__(192, 2)
xg_kernel(const float* __restrict__ x,
          const float* __restrict__ w_ih,
          const float* __restrict__ b_ih) {
    __shared__ __align__(16) float xs[128 * DD];  // 32 KB

    const int t   = blockIdx.x >> 2;
    const int b0  = (blockIdx.x & 3) * 128;
    const int tid = threadIdx.x;
    const int s   = tid & 1;        // lane-pair k-split
    const int q   = tid >> 1;       // [0,96): gate rows 4q..4q+3

    // Stage 128 rows of x into smem
    const float4* x4 = reinterpret_cast<const float4*>(x);
    float4* xs4 = reinterpret_cast<float4*>(xs);
    for (int i = tid; i < 128 * 16; i += 192) {
        int row = i >> 4, c4 = i & 15;
        xs4[i] = x4[((size_t)(b0 + row) * TT + t) * 16 + c4];
    }

    // Weights: rows 4q..4q+3, cols [32s, 32s+32) -> 64 ULL (128 regs)
    unsigned long long wq[64];  // wq[r*16 + j]
#pragma unroll
    for (int r = 0; r < 4; r++) {
        const unsigned long long* wp = reinterpret_cast<const unsigned long long*>(
            w_ih + (size_t)(4 * q + r) * DD + s * 32);
#pragma unroll
        for (int j = 0; j < 16; j++) wq[r * 16 + j] = wp[j];
    }
    // this thread stores rows {4q+2s, 4q+2s+1}
    const float2 bia = *reinterpret_cast<const float2*>(b_ih + 4 * q + 2 * s);

    __syncthreads();

    float* outp = g_xg + ((size_t)t * BB + b0) * GG + 4 * q + 2 * s;
#pragma unroll 1
    for (int row = 0; row < 128; row++) {
        const ulonglong2* hx =
            reinterpret_cast<const ulonglong2*>(xs + row * DD + s * 32);
        unsigned long long a0 = 0, a1 = 0, a2 = 0, a3 = 0;
#pragma unroll
        for (int i = 0; i < 8; i++) {
            ulonglong2 v = hx[i];
            a0 = ffma2(wq[2 * i],      v.x, a0);
            a0 = ffma2(wq[2 * i + 1],  v.y, a0);
            a1 = ffma2(wq[16 + 2 * i], v.x, a1);
            a1 = ffma2(wq[17 + 2 * i], v.y, a1);
            a2 = ffma2(wq[32 + 2 * i], v.x, a2);
            a2 = ffma2(wq[33 + 2 * i], v.y, a2);
            a3 = ffma2(wq[48 + 2 * i], v.x, a3);
            a3 = ffma2(wq[49 + 2 * i], v.y, a3);
        }
        float f0 = f2sum(a0), f1 = f2sum(a1), f2v = f2sum(a2), f3 = f2sum(a3);
        f0  += __shfl_xor_sync(0xffffffffu, f0, 1);
        f1  += __shfl_xor_sync(0xffffffffu, f1, 1);
        f2v += __shfl_xor_sync(0xffffffffu, f2v, 1);
        f3  += __shfl_xor_sync(0xffffffffu, f3, 1);
        float2 o = s ? make_float2(f2v, f3) : make_float2(f0, f1);
        *reinterpret_cast<float2*>(outp) = make_float2(o.x + bia.x, o.y + bia.y);
        outp += GG;
    }
}

// ============================================================================
// Kernel 2: persistent GRU recurrence. 128 CTAs x 4 batch rows, 768 threads.
// Thread (sw = tid/192, sl = tid&1, q = (tid%192)>>1) owns gate rows
// 4q..4q+3 x k-cols [16*(2sw+sl), +16): h reads halved vs R6 (256B/thread/
// step) -> crossbar demand ~= FMA floor. Lane-pair split combined by one
// shfl_xor(1) per row; P array stays [4][4][384] (R6 gate phase unchanged).
// ============================================================================
__global__ void __launch_bounds__(NTHR, 1)
gru_kernel(const float* __restrict__ mask,
           const float* __restrict__ w_hh,
           const float* __restrict__ b_hh,
           const float* __restrict__ Wo,
           const float* __restrict__ bo,
           float* __restrict__ out) {
    __shared__ __align__(16) float h_s[4][HH];      // 2 KB
    __shared__ __align__(16) float P_s[4][4][GG];   // 24 KB: [sw][batch][g]
    __shared__ float bh_s[GG];                      // b_hh copy (saves regs)
    __shared__ float m_s[4];
    __shared__ float wo_s[2][HH];

    const int tid  = threadIdx.x;
    const int lane = tid & 31;
    const int sw   = tid / 192;          // warp-level split (6 warps each)
    const int r192 = tid - sw * 192;
    const int sl   = r192 & 1;           // lane-pair split
    const int q    = r192 >> 1;          // [0,96): rows 4q..4q+3
    const int b0   = blockIdx.x * 4;

    for (int i = tid; i < 4 * HH; i += NTHR) (&h_s[0][0])[i] = 0.0f;
    for (int i = tid; i < 2 * HH; i += NTHR) (&wo_s[0][0])[i] = Wo[i];
    for (int i = tid; i < GG; i += NTHR) bh_s[i] = b_hh[i];

    // Weights: rows 4q..4q+3, cols [16*(2sw+sl), +16) -> 32 ULL (64 regs)
    const int coff = 16 * (2 * sw + sl);
    unsigned long long wq[32];  // wq[r*8 + j]
#pragma unroll
    for (int r = 0; r < 4; r++) {
        const unsigned long long* wp = reinterpret_cast<const unsigned long long*>(
            w_hh + (size_t)(4 * q + r) * HH + coff);
#pragma unroll
        for (int j = 0; j < 8; j++) wq[r * 8 + j] = wp[j];
    }

    const int cb = (tid >> 7) & 3;
    const int cj = tid & 127;
    const bool is_cell = tid < 512;

    const float* xg_cell = g_xg + ((size_t)(b0 + cb)) * GG + cj;
    const float* mp = mask + (size_t)(b0 + (tid & 3)) * TT;
    const float bo0 = bo[0], bo1 = bo[1];

    __syncthreads();

    for (int t = 0; t < TT; t++) {
        // ---- prefetch xg + mask; hidden under matvec ----
        float xr_v = 0.f, xz_v = 0.f, xn_v = 0.f;
        if (is_cell) {
            xr_v = xg_cell[0];
            xz_v = xg_cell[HH];
            xn_v = xg_cell[2 * HH];
        }
        if (tid < 4) m_s[tid] = mp[t];

        // ---- matvec: 4 batches; per batch 4 LDS.128 + 32 FFMA2 + 4 SHFL ----
#pragma unroll
        for (int b = 0; b < 4; b++) {
            const ulonglong2* hp =
                reinterpret_cast<const ulonglong2*>(&h_s[b][0] + coff);
            unsigned long long a0 = 0, a1 = 0, a2 = 0, a3 = 0;
#pragma unroll
            for (int i = 0; i < 4; i++) {
                ulonglong2 v = hp[i];
                a0 = ffma2(wq[2 * i],      v.x, a0);
                a0 = ffma2(wq[2 * i + 1],  v.y, a0);
                a1 = ffma2(wq[8 + 2 * i],  v.x, a1);
                a1 = ffma2(wq[9 + 2 * i],  v.y, a1);
                a2 = ffma2(wq[16 + 2 * i], v.x, a2);
                a2 = ffma2(wq[17 + 2 * i], v.y, a2);
                a3 = ffma2(wq[24 + 2 * i], v.x, a3);
                a3 = ffma2(wq[25 + 2 * i], v.y, a3);
            }
            float f0 = f2sum(a0), f1 = f2sum(a1), f2v = f2sum(a2), f3 = f2sum(a3);
            f0  += __shfl_xor_sync(0xffffffffu, f0, 1);
            f1  += __shfl_xor_sync(0xffffffffu, f1, 1);
            f2v += __shfl_xor_sync(0xffffffffu, f2v, 1);
            f3  += __shfl_xor_sync(0xffffffffu, f3, 1);
            if (sl == (b & 1))  // alternate lanes store alternate batches
                *reinterpret_cast<float4*>(&P_s[sw][b][4 * q]) =
                    make_float4(f0, f1, f2v, f3);
        }
        __syncthreads();

        // ---- gate phase: 512 cells, one per thread (warps 0-15) ----
        if (is_cell) {
            float sr = xr_v + bh_s[cj];
            float sz = xz_v + bh_s[cj + HH];
            float sn = bh_s[cj + 2 * HH];
#pragma unroll
            for (int k = 0; k < 4; k++) {
                sr += P_s[k][cb][cj];
                sz += P_s[k][cb][cj + HH];
                sn += P_s[k][cb][cj + 2 * HH];
            }
            float r  = sigmoid_fast(sr);
            float z  = sigmoid_fast(sz);
            float n  = tanh_fast(fmaf(r, sn, xn_v));
            float ho = h_s[cb][cj];
            float hnew = fmaf(z, ho - n, n);        // (1-z)*n + z*ho
            float m  = m_s[cb];
            h_s[cb][cj] = fmaf(m, hnew - ho, ho);   // m*hnew + (1-m)*ho
        }
        __syncthreads();

        // ---- logits on warps 16-23: overlaps next step's matvec ----
        if (tid >= 512) {
            int w = (tid - 512) >> 5;
            int b = w >> 1, o = w & 1;
            float pv = 0.0f;
#pragma unroll
            for (int qq = 0; qq < 4; qq++)
                pv = fmaf(h_s[b][lane + 32 * qq], wo_s[o][lane + 32 * qq], pv);
#pragma unroll
            for (int off = 16; off; off >>= 1)
                pv += __shfl_down_sync(0xffffffffu, pv, off);
            if (lane == 0)
                out[(((size_t)(b0 + b)) * TT + t) * 2 + o] = pv + (o ? bo1 : bo0);
        }

        xg_cell += (size_t)BB * GG;
    }
}

// ============================================================================
extern "C" void kernel_launch(void* const* d_in, const int* in_sizes, int n_in,
                              void* d_out, int out_size) {
    const float* x    = (const float*)d_in[0];
    const float* mask = (const float*)d_in[1];
    const float* w_ih = (const float*)d_in[2];
    const float* w_hh = (const float*)d_in[3];
    const float* b_ih = (const float*)d_in[4];
    const float* b_hh = (const float*)d_in[5];
    const float* Wo   = (const float*)d_in[6];
    const float* bo   = (const float*)d_in[7];
    float* out = (float*)d_out;

    xg_kernel<<<TT * 4, 192>>>(x, w_ih, b_ih);
    gru_kernel<<<BB / 4, NTHR>>>(mask, w_hh, b_hh, Wo, bo, out);
}

// round 9
// speedup vs baseline: 1.3742x; 1.0262x over previous
#include <cuda_runtime.h>
#include <cstdint>

// Problem constants
#define BB 512
#define TT 1024
#define DD 64
#define HH 128
#define GG 384   // 3*H
#define NTHR 768

// Scratch for precomputed input gates, layout [t][b][g]
__device__ float g_xg[(size_t)TT * BB * GG];

// ---------- packed fp32x2 helpers (PTX-only; ptxas won't auto-fuse) ----------
__device__ __forceinline__ unsigned long long ffma2(unsigned long long a,
                                                    unsigned long long b,
                                                    unsigned long long c) {
    unsigned long long d;
    asm("fma.rn.f32x2 %0, %1, %2, %3;" : "=l"(d) : "l"(a), "l"(b), "l"(c));
    return d;
}
__device__ __forceinline__ float f2sum(unsigned long long v) {
    float lo, hi;
    asm("mov.b64 {%0, %1}, %2;" : "=f"(lo), "=f"(hi) : "l"(v));
    return lo + hi;
}
__device__ __forceinline__ float tanh_fast(float x) {
    float y;
    asm("tanh.approx.f32 %0, %1;" : "=f"(y) : "f"(x));
    return y;
}
__device__ __forceinline__ float sigmoid_fast(float x) {
    return fmaf(tanh_fast(0.5f * x), 0.5f, 0.5f);
}

// ============================================================================
// Kernel 1: xg — UNCHANGED from R8 (1088us measured).
// ============================================================================
__global__ void __launch_bounds__(192, 2)
xg_kernel(const float* __restrict__ x,
          const float* __restrict__ w_ih,
          const float* __restrict__ b_ih) {
    __shared__ __align__(16) float xs[128 * DD];  // 32 KB

    const int t   = blockIdx.x >> 2;
    const int b0  = (blockIdx.x & 3) * 128;
    const int tid = threadIdx.x;
    const int s   = tid & 1;
    const int q   = tid >> 1;

    const float4* x4 = reinterpret_cast<const float4*>(x);
    float4* xs4 = reinterpret_cast<float4*>(xs);
    for (int i = tid; i < 128 * 16; i += 192) {
        int row = i >> 4, c4 = i & 15;
        xs4[i] = x4[((size_t)(b0 + row) * TT + t) * 16 + c4];
    }

    unsigned long long wq[64];
#pragma unroll
    for (int r = 0; r < 4; r++) {
        const unsigned long long* wp = reinterpret_cast<const unsigned long long*>(
            w_ih + (size_t)(4 * q + r) * DD + s * 32);
#pragma unroll
        for (int j = 0; j < 16; j++) wq[r * 16 + j] = wp[j];
    }
    const float2 bia = *reinterpret_cast<const float2*>(b_ih + 4 * q + 2 * s);

    __syncthreads();

    float* outp = g_xg + ((size_t)t * BB + b0) * GG + 4 * q + 2 * s;
#pragma unroll 1
    for (int row = 0; row < 128; row++) {
        const ulonglong2* hx =
            reinterpret_cast<const ulonglong2*>(xs + row * DD + s * 32);
        unsigned long long a0 = 0, a1 = 0, a2 = 0, a3 = 0;
#pragma unroll
        for (int i = 0; i < 8; i++) {
            ulonglong2 v = hx[i];
            a0 = ffma2(wq[2 * i],      v.x, a0);
            a0 = ffma2(wq[2 * i + 1],  v.y, a0);
            a1 = ffma2(wq[16 + 2 * i], v.x, a1);
            a1 = ffma2(wq[17 + 2 * i], v.y, a1);
            a2 = ffma2(wq[32 + 2 * i], v.x, a2);
            a2 = ffma2(wq[33 + 2 * i], v.y, a2);
            a3 = ffma2(wq[48 + 2 * i], v.x, a3);
            a3 = ffma2(wq[49 + 2 * i], v.y, a3);
        }
        float f0 = f2sum(a0), f1 = f2sum(a1), f2v = f2sum(a2), f3 = f2sum(a3);
        f0  += __shfl_xor_sync(0xffffffffu, f0, 1);
        f1  += __shfl_xor_sync(0xffffffffu, f1, 1);
        f2v += __shfl_xor_sync(0xffffffffu, f2v, 1);
        f3  += __shfl_xor_sync(0xffffffffu, f3, 1);
        float2 o = s ? make_float2(f2v, f3) : make_float2(f0, f1);
        *reinterpret_cast<float2*>(outp) = make_float2(o.x + bia.x, o.y + bia.y);
        outp += GG;
    }
}

// ============================================================================
// Kernel 2: persistent GRU recurrence. 128 CTAs x 4 batch rows, 768 threads.
// R8 geometry (4 rows x 16 cols/thread, 256B h-reads/step) but ALL 8 k-splits
// at WARP level: sw = tid/96 (96 = 3 warps -> warp-uniform), ZERO shfl.
// Every thread stores one float4 per batch into P_s[8][4][384] (49 KB).
// Gate phase sums 8 partials per gate (24 independent coalesced LDS.32).
// ============================================================================
__global__ void __launch_bounds__(NTHR, 1)
gru_kernel(const float* __restrict__ mask,
           const float* __restrict__ w_hh,
           const float* __restrict__ b_hh,
           const float* __restrict__ Wo,
           const float* __restrict__ bo,
           float* __restrict__ out) {
    __shared__ __align__(16) float h_s[4][HH];      // 2 KB
    __shared__ __align__(16) float P_s[8][4][GG];   // 49 KB: [split][batch][g]
    __shared__ float bh_s[GG];
    __shared__ float m_s[4];
    __shared__ float wo_s[2][HH];

    const int tid  = threadIdx.x;
    const int lane = tid & 31;
    const int sw   = tid / 96;           // k-split 0..7, warp-uniform
    const int q    = tid - sw * 96;      // [0,96): rows 4q..4q+3
    const int b0   = blockIdx.x * 4;

    for (int i = tid; i < 4 * HH; i += NTHR) (&h_s[0][0])[i] = 0.0f;
    for (int i = tid; i < 2 * HH; i += NTHR) (&wo_s[0][0])[i] = Wo[i];
    for (int i = tid; i < GG; i += NTHR) bh_s[i] = b_hh[i];

    // Weights: rows 4q..4q+3, cols [16*sw, +16) -> 32 ULL (64 regs)
    const int coff = 16 * sw;
    unsigned long long wq[32];  // wq[r*8 + j]
#pragma unroll
    for (int r = 0; r < 4; r++) {
        const unsigned long long* wp = reinterpret_cast<const unsigned long long*>(
            w_hh + (size_t)(4 * q + r) * HH + coff);
#pragma unroll
        for (int j = 0; j < 8; j++) wq[r * 8 + j] = wp[j];
    }

    const int cb = (tid >> 7) & 3;
    const int cj = tid & 127;
    const bool is_cell = tid < 512;

    const float* xg_cell = g_xg + ((size_t)(b0 + cb)) * GG + cj;
    const float* mp = mask + (size_t)(b0 + (tid & 3)) * TT;
    const float bo0 = bo[0], bo1 = bo[1];

    __syncthreads();

    for (int t = 0; t < TT; t++) {
        // ---- prefetch xg + mask; hidden under matvec ----
        float xr_v = 0.f, xz_v = 0.f, xn_v = 0.f;
        if (is_cell) {
            xr_v = xg_cell[0];
            xz_v = xg_cell[HH];
            xn_v = xg_cell[2 * HH];
        }
        if (tid < 4) m_s[tid] = mp[t];

        // ---- matvec: per batch 4 LDS.128 + 32 FFMA2 + 1 STS.128, no shfl ----
#pragma unroll
        for (int b = 0; b < 4; b++) {
            const ulonglong2* hp =
                reinterpret_cast<const ulonglong2*>(&h_s[b][0] + coff);
            unsigned long long a0 = 0, a1 = 0, a2 = 0, a3 = 0;
#pragma unroll
            for (int i = 0; i < 4; i++) {
                ulonglong2 v = hp[i];   // warp-uniform 16B load
                a0 = ffma2(wq[2 * i],      v.x, a0);
                a0 = ffma2(wq[2 * i + 1],  v.y, a0);
                a1 = ffma2(wq[8 + 2 * i],  v.x, a1);
                a1 = ffma2(wq[9 + 2 * i],  v.y, a1);
                a2 = ffma2(wq[16 + 2 * i], v.x, a2);
                a2 = ffma2(wq[17 + 2 * i], v.y, a2);
                a3 = ffma2(wq[24 + 2 * i], v.x, a3);
                a3 = ffma2(wq[25 + 2 * i], v.y, a3);
            }
            *reinterpret_cast<float4*>(&P_s[sw][b][4 * q]) =
                make_float4(f2sum(a0), f2sum(a1), f2sum(a2), f2sum(a3));
        }
        __syncthreads();

        // ---- gate phase: 512 cells, one per thread (warps 0-15) ----
        if (is_cell) {
            float sr = xr_v + bh_s[cj];
            float sz = xz_v + bh_s[cj + HH];
            float sn = bh_s[cj + 2 * HH];
#pragma unroll
            for (int k = 0; k < 8; k++) {
                sr += P_s[k][cb][cj];
                sz += P_s[k][cb][cj + HH];
                sn += P_s[k][cb][cj + 2 * HH];
            }
            float r  = sigmoid_fast(sr);
            float z  = sigmoid_fast(sz);
            float n  = tanh_fast(fmaf(r, sn, xn_v));
            float ho = h_s[cb][cj];
            float hnew = fmaf(z, ho - n, n);        // (1-z)*n + z*ho
            float m  = m_s[cb];
            h_s[cb][cj] = fmaf(m, hnew - ho, ho);   // m*hnew + (1-m)*ho
        }
        __syncthreads();

        // ---- logits on warps 16-23: overlaps next step's matvec ----
        if (tid >= 512) {
            int w = (tid - 512) >> 5;
            int b = w >> 1, o = w & 1;
            float pv = 0.0f;
#pragma unroll
            for (int qq = 0; qq < 4; qq++)
                pv = fmaf(h_s[b][lane + 32 * qq], wo_s[o][lane + 32 * qq], pv);
#pragma unroll
            for (int off = 16; off; off >>= 1)
                pv += __shfl_down_sync(0xffffffffu, pv, off);
            if (lane == 0)
                out[(((size_t)(b0 + b)) * TT + t) * 2 + o] = pv + (o ? bo1 : bo0);
        }

        xg_cell += (size_t)BB * GG;
    }
}

// ============================================================================
extern "C" void kernel_launch(void* const* d_in, const int* in_sizes, int n_in,
                              void* d_out, int out_size) {
    const float* x    = (const float*)d_in[0];
    const float* mask = (const float*)d_in[1];
    const float* w_ih = (const float*)d_in[2];
    const float* w_hh = (const float*)d_in[3];
    const float* b_ih = (const float*)d_in[4];
    const float* b_hh = (const float*)d_in[5];
    const float* Wo   = (const float*)d_in[6];
    const float* bo   = (const float*)d_in[7];
    float* out = (float*)d_out;

    xg_kernel<<<TT * 4, 192>>>(x, w_ih, b_ih);
    gru_kernel<<<BB / 4, NTHR>>>(mask, w_hh, b_hh, Wo, bo, out);
}